// round 4
// baseline (speedup 1.0000x reference)
#include <cuda_runtime.h>

#define NT  4096
#define DM  640
#define NH  10
#define DKH 64
#define HS  (NT * DKH)   // 262144 floats per head block

// Scratch (allocation-free rule: __device__ globals)
__device__ float g_Q[NT * DM];
__device__ float g_K[NT * DM];
__device__ float g_V[NT * DM];
__device__ float g_AO[NT * DM];

// ---------------------------------------------------------------------------
// QKV projection: C = x @ W^T   (x [NT,DM], W [DM,DM] row-major [out,in])
// 128x128 tile, BK=16, 256 threads, 8x8 micro-tile
// ---------------------------------------------------------------------------
__global__ __launch_bounds__(256) void qkv_gemm_kernel(
    const float* __restrict__ x,
    const float* __restrict__ Wq,
    const float* __restrict__ Wk,
    const float* __restrict__ Wv)
{
    constexpr int BM = 128, BK = 16;
    __shared__ float As[BK][BM];
    __shared__ float Bs[BK][BM];

    const float* W;
    float* C;
    if (blockIdx.z == 0)      { W = Wq; C = g_Q; }
    else if (blockIdx.z == 1) { W = Wk; C = g_K; }
    else                      { W = Wv; C = g_V; }

    const int m0 = blockIdx.y * BM;
    const int n0 = blockIdx.x * BM;
    const int tid = threadIdx.x;
    const int tx = tid & 15, ty = tid >> 4;
    const int lr = tid >> 2;           // 0..63
    const int lc = (tid & 3) << 2;     // 0,4,8,12

    float acc[8][8];
#pragma unroll
    for (int i = 0; i < 8; i++)
#pragma unroll
        for (int j = 0; j < 8; j++) acc[i][j] = 0.f;

    for (int k0 = 0; k0 < DM; k0 += BK) {
#pragma unroll
        for (int p = 0; p < 2; p++) {
            int r = lr + p * 64;
            float4 a = *(const float4*)(x + (size_t)(m0 + r) * DM + k0 + lc);
            As[lc + 0][r] = a.x; As[lc + 1][r] = a.y;
            As[lc + 2][r] = a.z; As[lc + 3][r] = a.w;
            float4 b = *(const float4*)(W + (size_t)(n0 + r) * DM + k0 + lc);
            Bs[lc + 0][r] = b.x; Bs[lc + 1][r] = b.y;
            Bs[lc + 2][r] = b.z; Bs[lc + 3][r] = b.w;
        }
        __syncthreads();
#pragma unroll
        for (int kk = 0; kk < BK; kk++) {
            float a[8], b[8];
#pragma unroll
            for (int i = 0; i < 8; i++) a[i] = As[kk][ty * 8 + i];
#pragma unroll
            for (int j = 0; j < 8; j++) b[j] = Bs[kk][tx * 8 + j];
#pragma unroll
            for (int i = 0; i < 8; i++)
#pragma unroll
                for (int j = 0; j < 8; j++) acc[i][j] += a[i] * b[j];
        }
        __syncthreads();
    }

#pragma unroll
    for (int i = 0; i < 8; i++) {
        float* dst = C + (size_t)(m0 + ty * 8 + i) * DM + n0 + tx * 8;
        *(float4*)(dst)     = make_float4(acc[i][0], acc[i][1], acc[i][2], acc[i][3]);
        *(float4*)(dst + 4) = make_float4(acc[i][4], acc[i][5], acc[i][6], acc[i][7]);
    }
}

// ---------------------------------------------------------------------------
// Fused attention per head (flat-reshape semantics):
//   A_h[m,d] = Q[base + m*64 + d]   (contiguous [4096,64])
//   B_h[d,n] = K[base + d*4096 + n] (contiguous [64,4096])
//   V_h[n,d] = V[base + n*64 + d]
//   O = (exp(A@B / 64) @ V) / rowsum(exp)   -- no max-sub needed (|s| << 1)
// CTA: 128 Q rows x full key sweep in 128-key tiles. 256 threads.
// Thread grid 16x16: S fragment 8 rows x 8 key-cols, O fragment 8 rows x 4 cols.
// ---------------------------------------------------------------------------
__global__ __launch_bounds__(256, 1) void attn_kernel()
{
    constexpr int BM = 128, BKY = 128;
    extern __shared__ float sm[];
    float* Qt = sm;                  // [64][128]  d-major, pre-scaled
    float* Bs = sm + 64 * 128;       // [64][128]  K slice
    float* Vs = sm + 2 * 64 * 128;   // [128][64]  V slice
    float* Pt = sm + 3 * 64 * 128;   // [128][128] exp(S) transposed (key-major)

    const int h  = blockIdx.y;
    const int m0 = blockIdx.x * BM;
    const float* Qp = g_Q + (size_t)h * HS;
    const float* Kp = g_K + (size_t)h * HS;
    const float* Vp = g_V + (size_t)h * HS;
    float*       Op = g_AO + (size_t)h * HS;
    const int tid = threadIdx.x;

    // Load Q tile transposed into Qt[d][r], pre-scaled by 1/sqrt(N)=1/64
    {
        const int rr = tid >> 4;            // 0..15
        const int d0 = (tid & 15) << 2;     // 0,4,...,60
#pragma unroll
        for (int p = 0; p < 8; p++) {
            int r = rr + p * 16;
            float4 q = *(const float4*)(Qp + (size_t)(m0 + r) * DKH + d0);
            Qt[(d0 + 0) * 128 + r] = q.x * 0.015625f;
            Qt[(d0 + 1) * 128 + r] = q.y * 0.015625f;
            Qt[(d0 + 2) * 128 + r] = q.z * 0.015625f;
            Qt[(d0 + 3) * 128 + r] = q.w * 0.015625f;
        }
    }

    const int tx = tid & 15, ty = tid >> 4;
    const int bd = tid >> 5;            // 0..7   (K-slice loader row)
    const int bc = (tid & 31) << 2;     // 0..124 (K-slice loader col4)

    float o[8][4];
    float l[8];
#pragma unroll
    for (int i = 0; i < 8; i++) {
        l[i] = 0.f;
#pragma unroll
        for (int c = 0; c < 4; c++) o[i][c] = 0.f;
    }

    for (int n0 = 0; n0 < NT; n0 += BKY) {
        __syncthreads();  // prev PV done before overwriting Bs/Vs (also covers Qt on iter 0)

        // Bs[d][j] = K[base + d*4096 + n0 + j]
#pragma unroll
        for (int p = 0; p < 8; p++) {
            int d = bd + p * 8;
            *(float4*)(Bs + d * 128 + bc) =
                *(const float4*)(Kp + (size_t)d * NT + n0 + bc);
        }
        // Vs: contiguous copy of V[base + n0*64 ...], 8192 floats
#pragma unroll
        for (int p = 0; p < 8; p++) {
            *(float4*)(Vs + tid * 4 + p * 1024) =
                *(const float4*)(Vp + (size_t)n0 * DKH + tid * 4 + p * 1024);
        }
        __syncthreads();

        // S = Qt^T @ Bs  -> s[8][8]
        float s[8][8];
#pragma unroll
        for (int i = 0; i < 8; i++)
#pragma unroll
            for (int j = 0; j < 8; j++) s[i][j] = 0.f;

#pragma unroll 4
        for (int d = 0; d < DKH; d++) {
            float a[8], b[8];
#pragma unroll
            for (int i = 0; i < 8; i++) a[i] = Qt[d * 128 + ty * 8 + i];
#pragma unroll
            for (int j = 0; j < 8; j++) b[j] = Bs[d * 128 + tx * 8 + j];
#pragma unroll
            for (int i = 0; i < 8; i++)
#pragma unroll
                for (int j = 0; j < 8; j++) s[i][j] += a[i] * b[j];
        }

        // exp (no max-sub: logits ~N(0,0.125^2)), row-sum partials, write Pt
#pragma unroll
        for (int j = 0; j < 8; j++) {
#pragma unroll
            for (int i = 0; i < 8; i++) {
                float p = __expf(s[i][j]);
                s[i][j] = p;
                l[i] += p;
            }
            float* dst = Pt + (tx * 8 + j) * 128 + ty * 8;
            *(float4*)(dst)     = make_float4(s[0][j], s[1][j], s[2][j], s[3][j]);
            *(float4*)(dst + 4) = make_float4(s[4][j], s[5][j], s[6][j], s[7][j]);
        }
        __syncthreads();

        // O += Pt^T @ Vs
#pragma unroll 4
        for (int j = 0; j < BKY; j++) {
            float a[8];
#pragma unroll
            for (int i = 0; i < 8; i++) a[i] = Pt[j * 128 + ty * 8 + i];
            float b0 = Vs[j * 64 + tx * 4 + 0];
            float b1 = Vs[j * 64 + tx * 4 + 1];
            float b2 = Vs[j * 64 + tx * 4 + 2];
            float b3 = Vs[j * 64 + tx * 4 + 3];
#pragma unroll
            for (int i = 0; i < 8; i++) {
                o[i][0] += a[i] * b0;
                o[i][1] += a[i] * b1;
                o[i][2] += a[i] * b2;
                o[i][3] += a[i] * b3;
            }
        }
    }

    // Reduce row sums across the 16 lanes (tx) sharing each row group
#pragma unroll
    for (int i = 0; i < 8; i++) {
        l[i] += __shfl_xor_sync(0xffffffffu, l[i], 8);
        l[i] += __shfl_xor_sync(0xffffffffu, l[i], 4);
        l[i] += __shfl_xor_sync(0xffffffffu, l[i], 2);
        l[i] += __shfl_xor_sync(0xffffffffu, l[i], 1);
    }

#pragma unroll
    for (int i = 0; i < 8; i++) {
        float inv = 1.0f / l[i];
        *(float4*)(Op + (size_t)(m0 + ty * 8 + i) * DKH + tx * 4) =
            make_float4(o[i][0] * inv, o[i][1] * inv, o[i][2] * inv, o[i][3] * inv);
    }
}

// ---------------------------------------------------------------------------
// Residual add + LayerNorm (biased variance, eps=1e-5), one CTA per row
// ---------------------------------------------------------------------------
__global__ __launch_bounds__(256) void ln_kernel(
    const float* __restrict__ x,
    const float* __restrict__ gamma,
    const float* __restrict__ beta,
    float* __restrict__ out)
{
    const int row = blockIdx.x;
    const int tid = threadIdx.x;
    const float* ao = g_AO + (size_t)row * DM;
    const float* xr = x    + (size_t)row * DM;

    float v[3];
    float sum = 0.f, ss = 0.f;
    int k = 0;
    for (int i = tid; i < DM; i += 256, k++) {
        float val = ao[i] + xr[i];
        v[k] = val;
        sum += val;
        ss  += val * val;
    }

#pragma unroll
    for (int off = 16; off > 0; off >>= 1) {
        sum += __shfl_xor_sync(0xffffffffu, sum, off);
        ss  += __shfl_xor_sync(0xffffffffu, ss,  off);
    }
    __shared__ float s1[8], s2[8];
    const int w = tid >> 5, lane = tid & 31;
    if (lane == 0) { s1[w] = sum; s2[w] = ss; }
    __syncthreads();
    if (w == 0) {
        sum = s1[lane & 7];
        ss  = s2[lane & 7];
#pragma unroll
        for (int off = 4; off > 0; off >>= 1) {
            sum += __shfl_xor_sync(0xffffffffu, sum, off);
            ss  += __shfl_xor_sync(0xffffffffu, ss,  off);
        }
        if (lane == 0) { s1[0] = sum; s2[0] = ss; }
    }
    __syncthreads();
    sum = s1[0]; ss = s2[0];

    const float mean = sum * (1.0f / DM);
    const float var  = ss * (1.0f / DM) - mean * mean;
    const float rstd = rsqrtf(var + 1e-5f);

    k = 0;
    for (int i = tid; i < DM; i += 256, k++) {
        out[(size_t)row * DM + i] = (v[k] - mean) * rstd * gamma[i] + beta[i];
    }
}

// ---------------------------------------------------------------------------
extern "C" void kernel_launch(void* const* d_in, const int* in_sizes, int n_in,
                              void* d_out, int out_size)
{
    const float* x     = (const float*)d_in[0];
    const float* Wq    = (const float*)d_in[1];
    const float* Wk    = (const float*)d_in[2];
    const float* Wv    = (const float*)d_in[3];
    const float* gamma = (const float*)d_in[4];
    const float* beta  = (const float*)d_in[5];
    float* out = (float*)d_out;

    const int attn_smem = (3 * 64 * 128 + 128 * 128) * (int)sizeof(float);  // 163840
    cudaFuncSetAttribute(attn_kernel,
                         cudaFuncAttributeMaxDynamicSharedMemorySize, attn_smem);

    qkv_gemm_kernel<<<dim3(DM / 128, NT / 128, 3), 256>>>(x, Wq, Wk, Wv);
    attn_kernel<<<dim3(NT / 128, NH), 256, attn_smem>>>();
    ln_kernel<<<NT, 256>>>(x, gamma, beta, out);
}

// round 8
// speedup vs baseline: 5.5925x; 5.5925x over previous
#include <cuda_runtime.h>
#include <cuda_bf16.h>
#include <cstdint>

#define NT  4096
#define DM  640
#define NH  10
#define DKH 64
#define HS  (NT * DKH)

// Scratch (allocation-free rule: __device__ globals). Q/K/V stored bf16.
__device__ __nv_bfloat16 g_Q[NT * DM];
__device__ __nv_bfloat16 g_K[NT * DM];
__device__ __nv_bfloat16 g_V[NT * DM];
__device__ float g_AO[NT * DM];

// ---------------------------------------------------------------------------
// Helpers (arch-neutral PTX: sm_80-era, accepted by target sm_103)
// ---------------------------------------------------------------------------
__device__ __forceinline__ uint32_t su32(const void* p) {
    uint32_t a;
    asm("{ .reg .u64 t; cvta.to.shared.u64 t, %1; cvt.u32.u64 %0, t; }"
        : "=r"(a) : "l"(p));
    return a;
}
// pack two f32 -> bf16x2 (lo = first arg)
__device__ __forceinline__ uint32_t packbf(float lo, float hi) {
    uint32_t r;
    asm("cvt.rn.bf16x2.f32 %0, %1, %2;" : "=r"(r) : "f"(hi), "f"(lo));
    return r;
}
__device__ __forceinline__ void ldsm4(uint32_t r[4], uint32_t a) {
    asm volatile("ldmatrix.sync.aligned.m8n8.x4.shared.b16 {%0,%1,%2,%3}, [%4];"
        : "=r"(r[0]), "=r"(r[1]), "=r"(r[2]), "=r"(r[3]) : "r"(a));
}
__device__ __forceinline__ void ldsm4t(uint32_t r[4], uint32_t a) {
    asm volatile("ldmatrix.sync.aligned.m8n8.x4.trans.shared.b16 {%0,%1,%2,%3}, [%4];"
        : "=r"(r[0]), "=r"(r[1]), "=r"(r[2]), "=r"(r[3]) : "r"(a));
}
__device__ __forceinline__ void mma16816(float* c, const uint32_t* a,
                                         uint32_t b0, uint32_t b1) {
    asm volatile("mma.sync.aligned.m16n8k16.row.col.f32.bf16.bf16.f32 "
        "{%0,%1,%2,%3}, {%4,%5,%6,%7}, {%8,%9}, {%0,%1,%2,%3};"
        : "+f"(c[0]), "+f"(c[1]), "+f"(c[2]), "+f"(c[3])
        : "r"(a[0]), "r"(a[1]), "r"(a[2]), "r"(a[3]), "r"(b0), "r"(b1));
}
__device__ __forceinline__ void cpa16(uint32_t s, const void* g) {
    asm volatile("cp.async.cg.shared.global [%0], [%1], 16;"
                 :: "r"(s), "l"(g) : "memory");
}
#define CP_COMMIT() asm volatile("cp.async.commit_group;" ::: "memory")
#define CP_WAIT(n)  asm volatile("cp.async.wait_group %0;" :: "n"(n) : "memory")

// ---------------------------------------------------------------------------
// QKV projection: C = x @ W^T (bf16 HMMA, fp32 accum), C stored bf16.
// BM=128, BN=128, BK=64, 256 threads (warp grid 2m x 4n, warp tile 64x32).
// Smem rows: [row][64k] bf16 = 128B, 16B-chunk swizzle c ^= row&7.
// ---------------------------------------------------------------------------
__global__ __launch_bounds__(256, 1) void qkv_mma_kernel(
    const float* __restrict__ x,  const float* __restrict__ Wq,
    const float* __restrict__ Wk, const float* __restrict__ Wv)
{
    extern __shared__ char dynsm[];   // 2 x (As 16KB + Bs 16KB) = 64KB

    const float* W; __nv_bfloat16* C; float cs;
    if (blockIdx.z == 0)      { W = Wq; C = g_Q; cs = 0.015625f; }  // fold 1/sqrt(N)
    else if (blockIdx.z == 1) { W = Wk; C = g_K; cs = 1.0f; }
    else                      { W = Wv; C = g_V; cs = 1.0f; }

    const int m0 = blockIdx.y * 128, n0 = blockIdx.x * 128;
    const int tid = threadIdx.x, lane = tid & 31, wid = tid >> 5;
    const int wm = wid & 1, wn = wid >> 1;
    const int l7 = lane & 7, l15 = lane & 15, hi = lane >> 4;
    const uint32_t smb = su32(dynsm);

    // loader: thread -> (row = tid/2, k-half = (tid&1)*32)
    const int lrow = tid >> 1, kh = (tid & 1) * 32;
    const float* xs = x + (size_t)(m0 + lrow) * DM + kh;
    const float* ws = W + (size_t)(n0 + lrow) * DM + kh;

    uint32_t stoff[4];
#pragma unroll
    for (int i = 0; i < 4; i++) {
        int c = 4 * (tid & 1) + i;
        stoff[i] = (uint32_t)(lrow * 128 + ((c ^ (lrow & 7)) * 16));
    }

    float acc[4][4][4];
#pragma unroll
    for (int i = 0; i < 4; i++)
#pragma unroll
        for (int j = 0; j < 4; j++)
#pragma unroll
            for (int k = 0; k < 4; k++) acc[i][j][k] = 0.f;

    uint32_t pkA[16], pkB[16];
#pragma unroll
    for (int i = 0; i < 8; i++) {
        float4 a = *(const float4*)(xs + i * 4);
        float4 b = *(const float4*)(ws + i * 4);
        pkA[2*i] = packbf(a.x, a.y); pkA[2*i+1] = packbf(a.z, a.w);
        pkB[2*i] = packbf(b.x, b.y); pkB[2*i+1] = packbf(b.z, b.w);
    }

    for (int kc = 0; kc < 10; kc++) {
        char* bufA = dynsm + (kc & 1) * 32768;
        char* bufB = bufA + 16384;
        const uint32_t Asu = smb + (kc & 1) * 32768;
        const uint32_t Bsu = Asu + 16384;
#pragma unroll
        for (int i = 0; i < 4; i++) {
            *(uint4*)(bufA + stoff[i]) =
                make_uint4(pkA[4*i], pkA[4*i+1], pkA[4*i+2], pkA[4*i+3]);
            *(uint4*)(bufB + stoff[i]) =
                make_uint4(pkB[4*i], pkB[4*i+1], pkB[4*i+2], pkB[4*i+3]);
        }
        __syncthreads();

        if (kc < 9) {
            const float* xs2 = xs + (kc + 1) * 64;
            const float* ws2 = ws + (kc + 1) * 64;
#pragma unroll
            for (int i = 0; i < 8; i++) {
                float4 a = *(const float4*)(xs2 + i * 4);
                float4 b = *(const float4*)(ws2 + i * 4);
                pkA[2*i] = packbf(a.x, a.y); pkA[2*i+1] = packbf(a.z, a.w);
                pkB[2*i] = packbf(b.x, b.y); pkB[2*i+1] = packbf(b.z, b.w);
            }
        }

#pragma unroll
        for (int kk = 0; kk < 4; kk++) {
            uint32_t af[4][4];
#pragma unroll
            for (int mi = 0; mi < 4; mi++)
                ldsm4(af[mi], Asu + (uint32_t)((wm*64 + mi*16 + l15) * 128
                              + (((2*kk + hi) ^ l7) * 16)));
            uint32_t bf2[2][4];
#pragma unroll
            for (int bi = 0; bi < 2; bi++)
                ldsm4(bf2[bi], Bsu + (uint32_t)((wn*32 + bi*16 + hi*8 + l7) * 128
                               + (((2*kk + ((lane >> 3) & 1)) ^ l7) * 16)));
#pragma unroll
            for (int mi = 0; mi < 4; mi++) {
                mma16816(acc[mi][0], af[mi], bf2[0][0], bf2[0][1]);
                mma16816(acc[mi][1], af[mi], bf2[0][2], bf2[0][3]);
                mma16816(acc[mi][2], af[mi], bf2[1][0], bf2[1][1]);
                mma16816(acc[mi][3], af[mi], bf2[1][2], bf2[1][3]);
            }
        }
        __syncthreads();
    }

    // epilogue: pack fp32 -> bf16 pairs, store
    const int r = lane >> 2, q = lane & 3;
#pragma unroll
    for (int mi = 0; mi < 4; mi++) {
        int row0 = m0 + wm*64 + mi*16 + r;
#pragma unroll
        for (int ni = 0; ni < 4; ni++) {
            int col = n0 + wn*32 + ni*8 + 2*q;
            uint32_t p0 = packbf(acc[mi][ni][0]*cs, acc[mi][ni][1]*cs);
            uint32_t p1 = packbf(acc[mi][ni][2]*cs, acc[mi][ni][3]*cs);
            *(uint32_t*)&C[(size_t)row0 * DM + col] = p0;
            *(uint32_t*)&C[(size_t)(row0 + 8) * DM + col] = p1;
        }
    }
}

// ---------------------------------------------------------------------------
// Fused attention (flat-reshape head semantics), bf16 HMMA.
// Per CTA: one head x 128 Q rows. 8 warps, each owns a 16-row stripe.
// Ks smem [64 d][128 key] = K native layout; Vs [128 key][64 d] = V native.
// Both feed ldmatrix.trans B-frags directly; P repacked in registers.
// ---------------------------------------------------------------------------
__global__ __launch_bounds__(256, 1) void attn_mma_kernel()
{
    extern __shared__ char dynsm[];
    // Qs 16KB | Ks[2] 2x16KB | Vs[2] 2x16KB  -> 80KB
    const uint32_t smQ = su32(dynsm);
    const uint32_t smK = smQ + 16384;
    const uint32_t smV = smQ + 49152;

    const int h  = blockIdx.y;
    const int m0 = blockIdx.x * 128;
    const __nv_bfloat16* Qp = g_Q + (size_t)h * HS;
    const __nv_bfloat16* Kp = g_K + (size_t)h * HS;
    const __nv_bfloat16* Vp = g_V + (size_t)h * HS;
    float* Op = g_AO + (size_t)h * HS;

    const int tid = threadIdx.x, lane = tid & 31, wid = tid >> 5;
    const int l7 = lane & 7, l15 = lane & 15, hi = lane >> 4;

    uint32_t sw16[8];
#pragma unroll
    for (int j = 0; j < 8; j++) sw16[j] = (uint32_t)(((2*j + hi) ^ l7) * 16);

    // ---- prologue: async Q + tiles 0,1 ----
#pragma unroll
    for (int i = 0; i < 4; i++) {
        int idx = tid + 256 * i;
        int row = idx >> 3, c = idx & 7;
        cpa16(smQ + row*128 + ((c ^ (row & 7)) * 16),
              Qp + (size_t)(m0 + row) * DKH + c*8);
    }
    CP_COMMIT();

#define LOAD_TILE(TT, B) do {                                              \
    int nb = (TT) * 128;                                                   \
    _Pragma("unroll")                                                      \
    for (int i = 0; i < 4; i++) {                                          \
        int idx = tid + 256 * i;                                           \
        int row = idx >> 4, c = idx & 15;                                  \
        cpa16(smK + (B)*16384 + row*256 + ((c ^ (row & 7)) * 16),          \
              Kp + (size_t)row * NT + nb + c*8);                           \
    }                                                                      \
    _Pragma("unroll")                                                      \
    for (int i = 0; i < 4; i++) {                                          \
        int idx = tid + 256 * i;                                           \
        int row = idx >> 3, c = idx & 7;                                   \
        cpa16(smV + (B)*16384 + row*128 + ((c ^ (row & 7)) * 16),          \
              Vp + (size_t)(nb + row) * DKH + c*8);                        \
    }                                                                      \
} while (0)

    LOAD_TILE(0, 0); CP_COMMIT();
    LOAD_TILE(1, 1); CP_COMMIT();
    CP_WAIT(1);            // Q + tile0 ready
    __syncthreads();

    // Q fragments (persistent)
    uint32_t qa[4][4];
#pragma unroll
    for (int kk = 0; kk < 4; kk++)
        ldsm4(qa[kk], smQ + (uint32_t)((16*wid + l15) * 128) + sw16[kk]);

    float oc[8][4];
#pragma unroll
    for (int j = 0; j < 8; j++)
#pragma unroll
        for (int k = 0; k < 4; k++) oc[j][k] = 0.f;
    float ls0 = 0.f, ls1 = 0.f;

    for (int t = 0; t < 32; t++) {
        const uint32_t Ksu = smK + (uint32_t)(t & 1) * 16384;
        const uint32_t Vsu = smV + (uint32_t)(t & 1) * 16384;

        // ---- MMA1: S[16,128] = Q @ K' ----
        float sc[16][4];
#pragma unroll
        for (int j = 0; j < 16; j++)
#pragma unroll
            for (int k = 0; k < 4; k++) sc[j][k] = 0.f;

#pragma unroll
        for (int kk = 0; kk < 4; kk++) {
#pragma unroll
            for (int jj = 0; jj < 8; jj++) {
                uint32_t bb[4];
                ldsm4t(bb, Ksu + (uint32_t)(kk*4096 + l15*256) + sw16[jj]);
                mma16816(sc[2*jj],     qa[kk], bb[0], bb[1]);
                mma16816(sc[2*jj + 1], qa[kk], bb[2], bb[3]);
            }
        }

        // ---- exp + register repack to P A-frags + rowsum ----
        uint32_t pa[8][4];
#pragma unroll
        for (int jj = 0; jj < 8; jj++) {
            float e00 = __expf(sc[2*jj][0]),   e01 = __expf(sc[2*jj][1]);
            float e02 = __expf(sc[2*jj][2]),   e03 = __expf(sc[2*jj][3]);
            float e10 = __expf(sc[2*jj+1][0]), e11 = __expf(sc[2*jj+1][1]);
            float e12 = __expf(sc[2*jj+1][2]), e13 = __expf(sc[2*jj+1][3]);
            ls0 += (e00 + e01) + (e10 + e11);
            ls1 += (e02 + e03) + (e12 + e13);
            pa[jj][0] = packbf(e00, e01);
            pa[jj][1] = packbf(e02, e03);
            pa[jj][2] = packbf(e10, e11);
            pa[jj][3] = packbf(e12, e13);
        }

        // ---- MMA2: O[16,64] += P @ V ----
#pragma unroll
        for (int kk = 0; kk < 8; kk++) {
#pragma unroll
            for (int jj = 0; jj < 4; jj++) {
                uint32_t bb[4];
                ldsm4t(bb, Vsu + (uint32_t)(kk*2048 + l15*128) + sw16[jj]);
                mma16816(oc[2*jj],     pa[kk], bb[0], bb[1]);
                mma16816(oc[2*jj + 1], pa[kk], bb[2], bb[3]);
            }
        }

        __syncthreads();   // all readers done before overwriting buf (t&1)
        if (t + 2 < 32) {
            LOAD_TILE(t + 2, t & 1);
            CP_COMMIT();
            CP_WAIT(1);    // tile t+1 guaranteed complete
        } else {
            CP_WAIT(0);
        }
        __syncthreads();
    }
#undef LOAD_TILE

    // rowsum reduce across the quad (lanes sharing a row)
    ls0 += __shfl_xor_sync(0xffffffffu, ls0, 1);
    ls0 += __shfl_xor_sync(0xffffffffu, ls0, 2);
    ls1 += __shfl_xor_sync(0xffffffffu, ls1, 1);
    ls1 += __shfl_xor_sync(0xffffffffu, ls1, 2);
    const float inv0 = 1.0f / ls0, inv1 = 1.0f / ls1;

    const int r = lane >> 2, q = lane & 3;
    const int row0 = m0 + 16*wid + r;
#pragma unroll
    for (int j = 0; j < 8; j++) {
        int d = 8*j + 2*q;
        *(float2*)(Op + (size_t)row0 * DKH + d) =
            make_float2(oc[j][0] * inv0, oc[j][1] * inv0);
        *(float2*)(Op + (size_t)(row0 + 8) * DKH + d) =
            make_float2(oc[j][2] * inv1, oc[j][3] * inv1);
    }
}

// ---------------------------------------------------------------------------
// Residual add + LayerNorm (biased variance, eps=1e-5), one CTA per row
// ---------------------------------------------------------------------------
__global__ __launch_bounds__(256) void ln_kernel(
    const float* __restrict__ x,
    const float* __restrict__ gamma,
    const float* __restrict__ beta,
    float* __restrict__ out)
{
    const int row = blockIdx.x;
    const int tid = threadIdx.x;
    const float* ao = g_AO + (size_t)row * DM;
    const float* xr = x    + (size_t)row * DM;

    float v[3];
    float sum = 0.f, ss = 0.f;
    int k = 0;
    for (int i = tid; i < DM; i += 256, k++) {
        float val = ao[i] + xr[i];
        v[k] = val;
        sum += val;
        ss  += val * val;
    }

#pragma unroll
    for (int off = 16; off > 0; off >>= 1) {
        sum += __shfl_xor_sync(0xffffffffu, sum, off);
        ss  += __shfl_xor_sync(0xffffffffu, ss,  off);
    }
    __shared__ float s1[8], s2[8];
    const int w = tid >> 5, lane = tid & 31;
    if (lane == 0) { s1[w] = sum; s2[w] = ss; }
    __syncthreads();
    if (w == 0) {
        sum = s1[lane & 7];
        ss  = s2[lane & 7];
#pragma unroll
        for (int off = 4; off > 0; off >>= 1) {
            sum += __shfl_xor_sync(0xffffffffu, sum, off);
            ss  += __shfl_xor_sync(0xffffffffu, ss,  off);
        }
        if (lane == 0) { s1[0] = sum; s2[0] = ss; }
    }
    __syncthreads();
    sum = s1[0]; ss = s2[0];

    const float mean = sum * (1.0f / DM);
    const float var  = ss * (1.0f / DM) - mean * mean;
    const float rstd = rsqrtf(var + 1e-5f);

    k = 0;
    for (int i = tid; i < DM; i += 256, k++) {
        out[(size_t)row * DM + i] = (v[k] - mean) * rstd * gamma[i] + beta[i];
    }
}

// ---------------------------------------------------------------------------
extern "C" void kernel_launch(void* const* d_in, const int* in_sizes, int n_in,
                              void* d_out, int out_size)
{
    const float* x     = (const float*)d_in[0];
    const float* Wq    = (const float*)d_in[1];
    const float* Wk    = (const float*)d_in[2];
    const float* Wv    = (const float*)d_in[3];
    const float* gamma = (const float*)d_in[4];
    const float* beta  = (const float*)d_in[5];
    float* out = (float*)d_out;

    const int qkv_smem  = 65536;   // 2 x (16KB A + 16KB B)
    const int attn_smem = 81920;   // Qs 16KB + Ks 2x16KB + Vs 2x16KB
    cudaFuncSetAttribute(qkv_mma_kernel,
                         cudaFuncAttributeMaxDynamicSharedMemorySize, qkv_smem);
    cudaFuncSetAttribute(attn_mma_kernel,
                         cudaFuncAttributeMaxDynamicSharedMemorySize, attn_smem);

    qkv_mma_kernel<<<dim3(DM / 128, NT / 128, 3), 256, qkv_smem>>>(x, Wq, Wk, Wv);
    attn_mma_kernel<<<dim3(NT / 128, NH), 256, attn_smem>>>();
    ln_kernel<<<NT, 256>>>(x, gamma, beta, out);
}

// round 9
// speedup vs baseline: 5.5968x; 1.0008x over previous
#include <cuda_runtime.h>
#include <cuda_bf16.h>
#include <cstdint>

#define NT  4096
#define DM  640
#define NH  10
#define DKH 64
#define HS  (NT * DKH)

// Scratch (allocation-free rule: __device__ globals). Q/K/V stored bf16.
__device__ __nv_bfloat16 g_Q[NT * DM];
__device__ __nv_bfloat16 g_K[NT * DM];
__device__ __nv_bfloat16 g_V[NT * DM];
__device__ float g_AO[NT * DM];

// ---------------------------------------------------------------------------
// Helpers (arch-neutral PTX: sm_80-era, accepted by target sm_103)
// ---------------------------------------------------------------------------
__device__ __forceinline__ uint32_t su32(const void* p) {
    uint32_t a;
    asm("{ .reg .u64 t; cvta.to.shared.u64 t, %1; cvt.u32.u64 %0, t; }"
        : "=r"(a) : "l"(p));
    return a;
}
// pack two f32 -> bf16x2 (lo = first arg)
__device__ __forceinline__ uint32_t packbf(float lo, float hi) {
    uint32_t r;
    asm("cvt.rn.bf16x2.f32 %0, %1, %2;" : "=r"(r) : "f"(hi), "f"(lo));
    return r;
}
__device__ __forceinline__ void ldsm4(uint32_t r[4], uint32_t a) {
    asm volatile("ldmatrix.sync.aligned.m8n8.x4.shared.b16 {%0,%1,%2,%3}, [%4];"
        : "=r"(r[0]), "=r"(r[1]), "=r"(r[2]), "=r"(r[3]) : "r"(a));
}
__device__ __forceinline__ void ldsm4t(uint32_t r[4], uint32_t a) {
    asm volatile("ldmatrix.sync.aligned.m8n8.x4.trans.shared.b16 {%0,%1,%2,%3}, [%4];"
        : "=r"(r[0]), "=r"(r[1]), "=r"(r[2]), "=r"(r[3]) : "r"(a));
}
__device__ __forceinline__ void mma16816(float* c, const uint32_t* a,
                                         uint32_t b0, uint32_t b1) {
    asm volatile("mma.sync.aligned.m16n8k16.row.col.f32.bf16.bf16.f32 "
        "{%0,%1,%2,%3}, {%4,%5,%6,%7}, {%8,%9}, {%0,%1,%2,%3};"
        : "+f"(c[0]), "+f"(c[1]), "+f"(c[2]), "+f"(c[3])
        : "r"(a[0]), "r"(a[1]), "r"(a[2]), "r"(a[3]), "r"(b0), "r"(b1));
}
__device__ __forceinline__ void cpa16(uint32_t s, const void* g) {
    asm volatile("cp.async.cg.shared.global [%0], [%1], 16;"
                 :: "r"(s), "l"(g) : "memory");
}
#define CP_COMMIT() asm volatile("cp.async.commit_group;" ::: "memory")
#define CP_WAIT(n)  asm volatile("cp.async.wait_group %0;" :: "n"(n) : "memory")

// ---------------------------------------------------------------------------
// QKV projection: C = x @ W^T (bf16 HMMA, fp32 accum), C stored bf16.
// BM=128, BN=128, BK=64, 256 threads (warp grid 2m x 4n, warp tile 64x32).
// Smem rows: [row][64k] bf16 = 128B, 16B-chunk swizzle c ^= row&7.
// ---------------------------------------------------------------------------
__global__ __launch_bounds__(256, 1) void qkv_mma_kernel(
    const float* __restrict__ x,  const float* __restrict__ Wq,
    const float* __restrict__ Wk, const float* __restrict__ Wv)
{
    extern __shared__ char dynsm[];   // 2 x (As 16KB + Bs 16KB) = 64KB

    const float* W; __nv_bfloat16* C; float cs;
    if (blockIdx.z == 0)      { W = Wq; C = g_Q; cs = 0.015625f; }  // fold 1/sqrt(N)
    else if (blockIdx.z == 1) { W = Wk; C = g_K; cs = 1.0f; }
    else                      { W = Wv; C = g_V; cs = 1.0f; }

    const int m0 = blockIdx.y * 128, n0 = blockIdx.x * 128;
    const int tid = threadIdx.x, lane = tid & 31, wid = tid >> 5;
    const int wm = wid & 1, wn = wid >> 1;
    const int l7 = lane & 7, l15 = lane & 15, hi = lane >> 4;
    const uint32_t smb = su32(dynsm);

    // loader: thread -> (row = tid/2, k-half = (tid&1)*32)
    const int lrow = tid >> 1, kh = (tid & 1) * 32;
    const float* xs = x + (size_t)(m0 + lrow) * DM + kh;
    const float* ws = W + (size_t)(n0 + lrow) * DM + kh;

    uint32_t stoff[4];
#pragma unroll
    for (int i = 0; i < 4; i++) {
        int c = 4 * (tid & 1) + i;
        stoff[i] = (uint32_t)(lrow * 128 + ((c ^ (lrow & 7)) * 16));
    }

    float acc[4][4][4];
#pragma unroll
    for (int i = 0; i < 4; i++)
#pragma unroll
        for (int j = 0; j < 4; j++)
#pragma unroll
            for (int k = 0; k < 4; k++) acc[i][j][k] = 0.f;

    uint32_t pkA[16], pkB[16];
#pragma unroll
    for (int i = 0; i < 8; i++) {
        float4 a = *(const float4*)(xs + i * 4);
        float4 b = *(const float4*)(ws + i * 4);
        pkA[2*i] = packbf(a.x, a.y); pkA[2*i+1] = packbf(a.z, a.w);
        pkB[2*i] = packbf(b.x, b.y); pkB[2*i+1] = packbf(b.z, b.w);
    }

    for (int kc = 0; kc < 10; kc++) {
        char* bufA = dynsm + (kc & 1) * 32768;
        char* bufB = bufA + 16384;
        const uint32_t Asu = smb + (kc & 1) * 32768;
        const uint32_t Bsu = Asu + 16384;
#pragma unroll
        for (int i = 0; i < 4; i++) {
            *(uint4*)(bufA + stoff[i]) =
                make_uint4(pkA[4*i], pkA[4*i+1], pkA[4*i+2], pkA[4*i+3]);
            *(uint4*)(bufB + stoff[i]) =
                make_uint4(pkB[4*i], pkB[4*i+1], pkB[4*i+2], pkB[4*i+3]);
        }
        __syncthreads();

        if (kc < 9) {
            const float* xs2 = xs + (kc + 1) * 64;
            const float* ws2 = ws + (kc + 1) * 64;
#pragma unroll
            for (int i = 0; i < 8; i++) {
                float4 a = *(const float4*)(xs2 + i * 4);
                float4 b = *(const float4*)(ws2 + i * 4);
                pkA[2*i] = packbf(a.x, a.y); pkA[2*i+1] = packbf(a.z, a.w);
                pkB[2*i] = packbf(b.x, b.y); pkB[2*i+1] = packbf(b.z, b.w);
            }
        }

#pragma unroll
        for (int kk = 0; kk < 4; kk++) {
            uint32_t af[4][4];
#pragma unroll
            for (int mi = 0; mi < 4; mi++)
                ldsm4(af[mi], Asu + (uint32_t)((wm*64 + mi*16 + l15) * 128
                              + (((2*kk + hi) ^ l7) * 16)));
            uint32_t bf2[2][4];
#pragma unroll
            for (int bi = 0; bi < 2; bi++)
                ldsm4(bf2[bi], Bsu + (uint32_t)((wn*32 + bi*16 + hi*8 + l7) * 128
                               + (((2*kk + ((lane >> 3) & 1)) ^ l7) * 16)));
#pragma unroll
            for (int mi = 0; mi < 4; mi++) {
                mma16816(acc[mi][0], af[mi], bf2[0][0], bf2[0][1]);
                mma16816(acc[mi][1], af[mi], bf2[0][2], bf2[0][3]);
                mma16816(acc[mi][2], af[mi], bf2[1][0], bf2[1][1]);
                mma16816(acc[mi][3], af[mi], bf2[1][2], bf2[1][3]);
            }
        }
        __syncthreads();
    }

    // epilogue: pack fp32 -> bf16 pairs, store
    const int r = lane >> 2, q = lane & 3;
#pragma unroll
    for (int mi = 0; mi < 4; mi++) {
        int row0 = m0 + wm*64 + mi*16 + r;
#pragma unroll
        for (int ni = 0; ni < 4; ni++) {
            int col = n0 + wn*32 + ni*8 + 2*q;
            uint32_t p0 = packbf(acc[mi][ni][0]*cs, acc[mi][ni][1]*cs);
            uint32_t p1 = packbf(acc[mi][ni][2]*cs, acc[mi][ni][3]*cs);
            *(uint32_t*)&C[(size_t)row0 * DM + col] = p0;
            *(uint32_t*)&C[(size_t)(row0 + 8) * DM + col] = p1;
        }
    }
}

// ---------------------------------------------------------------------------
// Fused attention (flat-reshape head semantics), bf16 HMMA.
// Per CTA: one head x 128 Q rows. 8 warps, each owns a 16-row stripe.
// Ks smem [64 d][128 key] = K native layout; Vs [128 key][64 d] = V native.
// Both feed ldmatrix.trans B-frags directly; P repacked in registers.
// ---------------------------------------------------------------------------
__global__ __launch_bounds__(256, 1) void attn_mma_kernel()
{
    extern __shared__ char dynsm[];
    // Qs 16KB | Ks[2] 2x16KB | Vs[2] 2x16KB  -> 80KB
    const uint32_t smQ = su32(dynsm);
    const uint32_t smK = smQ + 16384;
    const uint32_t smV = smQ + 49152;

    const int h  = blockIdx.y;
    const int m0 = blockIdx.x * 128;
    const __nv_bfloat16* Qp = g_Q + (size_t)h * HS;
    const __nv_bfloat16* Kp = g_K + (size_t)h * HS;
    const __nv_bfloat16* Vp = g_V + (size_t)h * HS;
    float* Op = g_AO + (size_t)h * HS;

    const int tid = threadIdx.x, lane = tid & 31, wid = tid >> 5;
    const int l7 = lane & 7, l15 = lane & 15, hi = lane >> 4;

    uint32_t sw16[8];
#pragma unroll
    for (int j = 0; j < 8; j++) sw16[j] = (uint32_t)(((2*j + hi) ^ l7) * 16);

    // ---- prologue: async Q + tiles 0,1 ----
#pragma unroll
    for (int i = 0; i < 4; i++) {
        int idx = tid + 256 * i;
        int row = idx >> 3, c = idx & 7;
        cpa16(smQ + row*128 + ((c ^ (row & 7)) * 16),
              Qp + (size_t)(m0 + row) * DKH + c*8);
    }
    CP_COMMIT();

#define LOAD_TILE(TT, B) do {                                              \
    int nb = (TT) * 128;                                                   \
    _Pragma("unroll")                                                      \
    for (int i = 0; i < 4; i++) {                                          \
        int idx = tid + 256 * i;                                           \
        int row = idx >> 4, c = idx & 15;                                  \
        cpa16(smK + (B)*16384 + row*256 + ((c ^ (row & 7)) * 16),          \
              Kp + (size_t)row * NT + nb + c*8);                           \
    }                                                                      \
    _Pragma("unroll")                                                      \
    for (int i = 0; i < 4; i++) {                                          \
        int idx = tid + 256 * i;                                           \
        int row = idx >> 3, c = idx & 7;                                   \
        cpa16(smV + (B)*16384 + row*128 + ((c ^ (row & 7)) * 16),          \
              Vp + (size_t)(nb + row) * DKH + c*8);                        \
    }                                                                      \
} while (0)

    LOAD_TILE(0, 0); CP_COMMIT();
    LOAD_TILE(1, 1); CP_COMMIT();
    CP_WAIT(1);            // Q + tile0 ready
    __syncthreads();

    // Q fragments (persistent)
    uint32_t qa[4][4];
#pragma unroll
    for (int kk = 0; kk < 4; kk++)
        ldsm4(qa[kk], smQ + (uint32_t)((16*wid + l15) * 128) + sw16[kk]);

    float oc[8][4];
#pragma unroll
    for (int j = 0; j < 8; j++)
#pragma unroll
        for (int k = 0; k < 4; k++) oc[j][k] = 0.f;
    float ls0 = 0.f, ls1 = 0.f;

    for (int t = 0; t < 32; t++) {
        const uint32_t Ksu = smK + (uint32_t)(t & 1) * 16384;
        const uint32_t Vsu = smV + (uint32_t)(t & 1) * 16384;

        // ---- MMA1: S[16,128] = Q @ K' ----
        float sc[16][4];
#pragma unroll
        for (int j = 0; j < 16; j++)
#pragma unroll
            for (int k = 0; k < 4; k++) sc[j][k] = 0.f;

#pragma unroll
        for (int kk = 0; kk < 4; kk++) {
#pragma unroll
            for (int jj = 0; jj < 8; jj++) {
                uint32_t bb[4];
                ldsm4t(bb, Ksu + (uint32_t)(kk*4096 + l15*256) + sw16[jj]);
                mma16816(sc[2*jj],     qa[kk], bb[0], bb[1]);
                mma16816(sc[2*jj + 1], qa[kk], bb[2], bb[3]);
            }
        }

        // ---- exp + register repack to P A-frags + rowsum ----
        uint32_t pa[8][4];
#pragma unroll
        for (int jj = 0; jj < 8; jj++) {
            float e00 = __expf(sc[2*jj][0]),   e01 = __expf(sc[2*jj][1]);
            float e02 = __expf(sc[2*jj][2]),   e03 = __expf(sc[2*jj][3]);
            float e10 = __expf(sc[2*jj+1][0]), e11 = __expf(sc[2*jj+1][1]);
            float e12 = __expf(sc[2*jj+1][2]), e13 = __expf(sc[2*jj+1][3]);
            ls0 += (e00 + e01) + (e10 + e11);
            ls1 += (e02 + e03) + (e12 + e13);
            pa[jj][0] = packbf(e00, e01);
            pa[jj][1] = packbf(e02, e03);
            pa[jj][2] = packbf(e10, e11);
            pa[jj][3] = packbf(e12, e13);
        }

        // ---- MMA2: O[16,64] += P @ V ----
#pragma unroll
        for (int kk = 0; kk < 8; kk++) {
#pragma unroll
            for (int jj = 0; jj < 4; jj++) {
                uint32_t bb[4];
                ldsm4t(bb, Vsu + (uint32_t)(kk*2048 + l15*128) + sw16[jj]);
                mma16816(oc[2*jj],     pa[kk], bb[0], bb[1]);
                mma16816(oc[2*jj + 1], pa[kk], bb[2], bb[3]);
            }
        }

        __syncthreads();   // all readers done before overwriting buf (t&1)
        if (t + 2 < 32) {
            LOAD_TILE(t + 2, t & 1);
            CP_COMMIT();
            CP_WAIT(1);    // tile t+1 guaranteed complete
        } else {
            CP_WAIT(0);
        }
        __syncthreads();
    }
#undef LOAD_TILE

    // rowsum reduce across the quad (lanes sharing a row)
    ls0 += __shfl_xor_sync(0xffffffffu, ls0, 1);
    ls0 += __shfl_xor_sync(0xffffffffu, ls0, 2);
    ls1 += __shfl_xor_sync(0xffffffffu, ls1, 1);
    ls1 += __shfl_xor_sync(0xffffffffu, ls1, 2);
    const float inv0 = 1.0f / ls0, inv1 = 1.0f / ls1;

    const int r = lane >> 2, q = lane & 3;
    const int row0 = m0 + 16*wid + r;
#pragma unroll
    for (int j = 0; j < 8; j++) {
        int d = 8*j + 2*q;
        *(float2*)(Op + (size_t)row0 * DKH + d) =
            make_float2(oc[j][0] * inv0, oc[j][1] * inv0);
        *(float2*)(Op + (size_t)(row0 + 8) * DKH + d) =
            make_float2(oc[j][2] * inv1, oc[j][3] * inv1);
    }
}

// ---------------------------------------------------------------------------
// Residual add + LayerNorm (biased variance, eps=1e-5), one CTA per row
// ---------------------------------------------------------------------------
__global__ __launch_bounds__(256) void ln_kernel(
    const float* __restrict__ x,
    const float* __restrict__ gamma,
    const float* __restrict__ beta,
    float* __restrict__ out)
{
    const int row = blockIdx.x;
    const int tid = threadIdx.x;
    const float* ao = g_AO + (size_t)row * DM;
    const float* xr = x    + (size_t)row * DM;

    float v[3];
    float sum = 0.f, ss = 0.f;
    int k = 0;
    for (int i = tid; i < DM; i += 256, k++) {
        float val = ao[i] + xr[i];
        v[k] = val;
        sum += val;
        ss  += val * val;
    }

#pragma unroll
    for (int off = 16; off > 0; off >>= 1) {
        sum += __shfl_xor_sync(0xffffffffu, sum, off);
        ss  += __shfl_xor_sync(0xffffffffu, ss,  off);
    }
    __shared__ float s1[8], s2[8];
    const int w = tid >> 5, lane = tid & 31;
    if (lane == 0) { s1[w] = sum; s2[w] = ss; }
    __syncthreads();
    if (w == 0) {
        sum = s1[lane & 7];
        ss  = s2[lane & 7];
#pragma unroll
        for (int off = 4; off > 0; off >>= 1) {
            sum += __shfl_xor_sync(0xffffffffu, sum, off);
            ss  += __shfl_xor_sync(0xffffffffu, ss,  off);
        }
        if (lane == 0) { s1[0] = sum; s2[0] = ss; }
    }
    __syncthreads();
    sum = s1[0]; ss = s2[0];

    const float mean = sum * (1.0f / DM);
    const float var  = ss * (1.0f / DM) - mean * mean;
    const float rstd = rsqrtf(var + 1e-5f);

    k = 0;
    for (int i = tid; i < DM; i += 256, k++) {
        out[(size_t)row * DM + i] = (v[k] - mean) * rstd * gamma[i] + beta[i];
    }
}

// ---------------------------------------------------------------------------
extern "C" void kernel_launch(void* const* d_in, const int* in_sizes, int n_in,
                              void* d_out, int out_size)
{
    const float* x     = (const float*)d_in[0];
    const float* Wq    = (const float*)d_in[1];
    const float* Wk    = (const float*)d_in[2];
    const float* Wv    = (const float*)d_in[3];
    const float* gamma = (const float*)d_in[4];
    const float* beta  = (const float*)d_in[5];
    float* out = (float*)d_out;

    const int qkv_smem  = 65536;   // 2 x (16KB A + 16KB B)
    const int attn_smem = 81920;   // Qs 16KB + Ks 2x16KB + Vs 2x16KB
    cudaFuncSetAttribute(qkv_mma_kernel,
                         cudaFuncAttributeMaxDynamicSharedMemorySize, qkv_smem);
    cudaFuncSetAttribute(attn_mma_kernel,
                         cudaFuncAttributeMaxDynamicSharedMemorySize, attn_smem);

    qkv_mma_kernel<<<dim3(DM / 128, NT / 128, 3), 256, qkv_smem>>>(x, Wq, Wk, Wv);
    attn_mma_kernel<<<dim3(NT / 128, NH), 256, attn_smem>>>();
    ln_kernel<<<NT, 256>>>(x, gamma, beta, out);
}

// round 10
// speedup vs baseline: 5.5980x; 1.0002x over previous
#include <cuda_runtime.h>
#include <cuda_bf16.h>
#include <cstdint>

#define NT  4096
#define DM  640
#define NH  10
#define DKH 64
#define HS  (NT * DKH)

// Scratch (allocation-free rule: __device__ globals). Q/K/V stored bf16.
__device__ __nv_bfloat16 g_Q[NT * DM];
__device__ __nv_bfloat16 g_K[NT * DM];
__device__ __nv_bfloat16 g_V[NT * DM];
__device__ float g_AO[NT * DM];

// ---------------------------------------------------------------------------
// Helpers (arch-neutral PTX: sm_80-era, accepted by target sm_103)
// ---------------------------------------------------------------------------
__device__ __forceinline__ uint32_t su32(const void* p) {
    uint32_t a;
    asm("{ .reg .u64 t; cvta.to.shared.u64 t, %1; cvt.u32.u64 %0, t; }"
        : "=r"(a) : "l"(p));
    return a;
}
// pack two f32 -> bf16x2 (lo = first arg)
__device__ __forceinline__ uint32_t packbf(float lo, float hi) {
    uint32_t r;
    asm("cvt.rn.bf16x2.f32 %0, %1, %2;" : "=r"(r) : "f"(hi), "f"(lo));
    return r;
}
__device__ __forceinline__ void ldsm4(uint32_t r[4], uint32_t a) {
    asm volatile("ldmatrix.sync.aligned.m8n8.x4.shared.b16 {%0,%1,%2,%3}, [%4];"
        : "=r"(r[0]), "=r"(r[1]), "=r"(r[2]), "=r"(r[3]) : "r"(a));
}
__device__ __forceinline__ void ldsm4t(uint32_t r[4], uint32_t a) {
    asm volatile("ldmatrix.sync.aligned.m8n8.x4.trans.shared.b16 {%0,%1,%2,%3}, [%4];"
        : "=r"(r[0]), "=r"(r[1]), "=r"(r[2]), "=r"(r[3]) : "r"(a));
}
__device__ __forceinline__ void mma16816(float* c, const uint32_t* a,
                                         uint32_t b0, uint32_t b1) {
    asm volatile("mma.sync.aligned.m16n8k16.row.col.f32.bf16.bf16.f32 "
        "{%0,%1,%2,%3}, {%4,%5,%6,%7}, {%8,%9}, {%0,%1,%2,%3};"
        : "+f"(c[0]), "+f"(c[1]), "+f"(c[2]), "+f"(c[3])
        : "r"(a[0]), "r"(a[1]), "r"(a[2]), "r"(a[3]), "r"(b0), "r"(b1));
}
__device__ __forceinline__ void cpa16(uint32_t s, const void* g) {
    asm volatile("cp.async.cg.shared.global [%0], [%1], 16;"
                 :: "r"(s), "l"(g) : "memory");
}
#define CP_COMMIT() asm volatile("cp.async.commit_group;" ::: "memory")
#define CP_WAIT(n)  asm volatile("cp.async.wait_group %0;" :: "n"(n) : "memory")

// ---------------------------------------------------------------------------
// QKV projection: C = x @ W^T (bf16 HMMA, fp32 accum), C stored bf16.
// BM=128, BN=128, BK=64, 256 threads (warp grid 2m x 4n, warp tile 64x32).
// Smem rows: [row][64k] bf16 = 128B, 16B-chunk swizzle c ^= row&7.
// ---------------------------------------------------------------------------
__global__ __launch_bounds__(256, 1) void qkv_mma_kernel(
    const float* __restrict__ x,  const float* __restrict__ Wq,
    const float* __restrict__ Wk, const float* __restrict__ Wv)
{
    extern __shared__ char dynsm[];   // 2 x (As 16KB + Bs 16KB) = 64KB

    const float* W; __nv_bfloat16* C; float cs;
    if (blockIdx.z == 0)      { W = Wq; C = g_Q; cs = 0.015625f; }  // fold 1/sqrt(N)
    else if (blockIdx.z == 1) { W = Wk; C = g_K; cs = 1.0f; }
    else                      { W = Wv; C = g_V; cs = 1.0f; }

    const int m0 = blockIdx.y * 128, n0 = blockIdx.x * 128;
    const int tid = threadIdx.x, lane = tid & 31, wid = tid >> 5;
    const int wm = wid & 1, wn = wid >> 1;
    const int l7 = lane & 7, l15 = lane & 15, hi = lane >> 4;
    const uint32_t smb = su32(dynsm);

    // loader: thread -> (row = tid/2, k-half = (tid&1)*32)
    const int lrow = tid >> 1, kh = (tid & 1) * 32;
    const float* xs = x + (size_t)(m0 + lrow) * DM + kh;
    const float* ws = W + (size_t)(n0 + lrow) * DM + kh;

    uint32_t stoff[4];
#pragma unroll
    for (int i = 0; i < 4; i++) {
        int c = 4 * (tid & 1) + i;
        stoff[i] = (uint32_t)(lrow * 128 + ((c ^ (lrow & 7)) * 16));
    }

    float acc[4][4][4];
#pragma unroll
    for (int i = 0; i < 4; i++)
#pragma unroll
        for (int j = 0; j < 4; j++)
#pragma unroll
            for (int k = 0; k < 4; k++) acc[i][j][k] = 0.f;

    uint32_t pkA[16], pkB[16];
#pragma unroll
    for (int i = 0; i < 8; i++) {
        float4 a = *(const float4*)(xs + i * 4);
        float4 b = *(const float4*)(ws + i * 4);
        pkA[2*i] = packbf(a.x, a.y); pkA[2*i+1] = packbf(a.z, a.w);
        pkB[2*i] = packbf(b.x, b.y); pkB[2*i+1] = packbf(b.z, b.w);
    }

    for (int kc = 0; kc < 10; kc++) {
        char* bufA = dynsm + (kc & 1) * 32768;
        char* bufB = bufA + 16384;
        const uint32_t Asu = smb + (kc & 1) * 32768;
        const uint32_t Bsu = Asu + 16384;
#pragma unroll
        for (int i = 0; i < 4; i++) {
            *(uint4*)(bufA + stoff[i]) =
                make_uint4(pkA[4*i], pkA[4*i+1], pkA[4*i+2], pkA[4*i+3]);
            *(uint4*)(bufB + stoff[i]) =
                make_uint4(pkB[4*i], pkB[4*i+1], pkB[4*i+2], pkB[4*i+3]);
        }
        __syncthreads();

        if (kc < 9) {
            const float* xs2 = xs + (kc + 1) * 64;
            const float* ws2 = ws + (kc + 1) * 64;
#pragma unroll
            for (int i = 0; i < 8; i++) {
                float4 a = *(const float4*)(xs2 + i * 4);
                float4 b = *(const float4*)(ws2 + i * 4);
                pkA[2*i] = packbf(a.x, a.y); pkA[2*i+1] = packbf(a.z, a.w);
                pkB[2*i] = packbf(b.x, b.y); pkB[2*i+1] = packbf(b.z, b.w);
            }
        }

#pragma unroll
        for (int kk = 0; kk < 4; kk++) {
            uint32_t af[4][4];
#pragma unroll
            for (int mi = 0; mi < 4; mi++)
                ldsm4(af[mi], Asu + (uint32_t)((wm*64 + mi*16 + l15) * 128
                              + (((2*kk + hi) ^ l7) * 16)));
            uint32_t bf2[2][4];
#pragma unroll
            for (int bi = 0; bi < 2; bi++)
                ldsm4(bf2[bi], Bsu + (uint32_t)((wn*32 + bi*16 + hi*8 + l7) * 128
                               + (((2*kk + ((lane >> 3) & 1)) ^ l7) * 16)));
#pragma unroll
            for (int mi = 0; mi < 4; mi++) {
                mma16816(acc[mi][0], af[mi], bf2[0][0], bf2[0][1]);
                mma16816(acc[mi][1], af[mi], bf2[0][2], bf2[0][3]);
                mma16816(acc[mi][2], af[mi], bf2[1][0], bf2[1][1]);
                mma16816(acc[mi][3], af[mi], bf2[1][2], bf2[1][3]);
            }
        }
        __syncthreads();
    }

    // epilogue: pack fp32 -> bf16 pairs, store
    const int r = lane >> 2, q = lane & 3;
#pragma unroll
    for (int mi = 0; mi < 4; mi++) {
        int row0 = m0 + wm*64 + mi*16 + r;
#pragma unroll
        for (int ni = 0; ni < 4; ni++) {
            int col = n0 + wn*32 + ni*8 + 2*q;
            uint32_t p0 = packbf(acc[mi][ni][0]*cs, acc[mi][ni][1]*cs);
            uint32_t p1 = packbf(acc[mi][ni][2]*cs, acc[mi][ni][3]*cs);
            *(uint32_t*)&C[(size_t)row0 * DM + col] = p0;
            *(uint32_t*)&C[(size_t)(row0 + 8) * DM + col] = p1;
        }
    }
}

// ---------------------------------------------------------------------------
// Fused attention (flat-reshape head semantics), bf16 HMMA.
// Per CTA: one head x 128 Q rows. 8 warps, each owns a 16-row stripe.
// Ks smem [64 d][128 key] = K native layout; Vs [128 key][64 d] = V native.
// Both feed ldmatrix.trans B-frags directly; P repacked in registers.
// ---------------------------------------------------------------------------
__global__ __launch_bounds__(256, 1) void attn_mma_kernel()
{
    extern __shared__ char dynsm[];
    // Qs 16KB | Ks[2] 2x16KB | Vs[2] 2x16KB  -> 80KB
    const uint32_t smQ = su32(dynsm);
    const uint32_t smK = smQ + 16384;
    const uint32_t smV = smQ + 49152;

    const int h  = blockIdx.y;
    const int m0 = blockIdx.x * 128;
    const __nv_bfloat16* Qp = g_Q + (size_t)h * HS;
    const __nv_bfloat16* Kp = g_K + (size_t)h * HS;
    const __nv_bfloat16* Vp = g_V + (size_t)h * HS;
    float* Op = g_AO + (size_t)h * HS;

    const int tid = threadIdx.x, lane = tid & 31, wid = tid >> 5;
    const int l7 = lane & 7, l15 = lane & 15, hi = lane >> 4;

    uint32_t sw16[8];
#pragma unroll
    for (int j = 0; j < 8; j++) sw16[j] = (uint32_t)(((2*j + hi) ^ l7) * 16);

    // ---- prologue: async Q + tiles 0,1 ----
#pragma unroll
    for (int i = 0; i < 4; i++) {
        int idx = tid + 256 * i;
        int row = idx >> 3, c = idx & 7;
        cpa16(smQ + row*128 + ((c ^ (row & 7)) * 16),
              Qp + (size_t)(m0 + row) * DKH + c*8);
    }
    CP_COMMIT();

#define LOAD_TILE(TT, B) do {                                              \
    int nb = (TT) * 128;                                                   \
    _Pragma("unroll")                                                      \
    for (int i = 0; i < 4; i++) {                                          \
        int idx = tid + 256 * i;                                           \
        int row = idx >> 4, c = idx & 15;                                  \
        cpa16(smK + (B)*16384 + row*256 + ((c ^ (row & 7)) * 16),          \
              Kp + (size_t)row * NT + nb + c*8);                           \
    }                                                                      \
    _Pragma("unroll")                                                      \
    for (int i = 0; i < 4; i++) {                                          \
        int idx = tid + 256 * i;                                           \
        int row = idx >> 3, c = idx & 7;                                   \
        cpa16(smV + (B)*16384 + row*128 + ((c ^ (row & 7)) * 16),          \
              Vp + (size_t)(nb + row) * DKH + c*8);                        \
    }                                                                      \
} while (0)

    LOAD_TILE(0, 0); CP_COMMIT();
    LOAD_TILE(1, 1); CP_COMMIT();
    CP_WAIT(1);            // Q + tile0 ready
    __syncthreads();

    // Q fragments (persistent)
    uint32_t qa[4][4];
#pragma unroll
    for (int kk = 0; kk < 4; kk++)
        ldsm4(qa[kk], smQ + (uint32_t)((16*wid + l15) * 128) + sw16[kk]);

    float oc[8][4];
#pragma unroll
    for (int j = 0; j < 8; j++)
#pragma unroll
        for (int k = 0; k < 4; k++) oc[j][k] = 0.f;
    float ls0 = 0.f, ls1 = 0.f;

    for (int t = 0; t < 32; t++) {
        const uint32_t Ksu = smK + (uint32_t)(t & 1) * 16384;
        const uint32_t Vsu = smV + (uint32_t)(t & 1) * 16384;

        // ---- MMA1: S[16,128] = Q @ K' ----
        float sc[16][4];
#pragma unroll
        for (int j = 0; j < 16; j++)
#pragma unroll
            for (int k = 0; k < 4; k++) sc[j][k] = 0.f;

#pragma unroll
        for (int kk = 0; kk < 4; kk++) {
#pragma unroll
            for (int jj = 0; jj < 8; jj++) {
                uint32_t bb[4];
                ldsm4t(bb, Ksu + (uint32_t)(kk*4096 + l15*256) + sw16[jj]);
                mma16816(sc[2*jj],     qa[kk], bb[0], bb[1]);
                mma16816(sc[2*jj + 1], qa[kk], bb[2], bb[3]);
            }
        }

        // ---- exp + register repack to P A-frags + rowsum ----
        uint32_t pa[8][4];
#pragma unroll
        for (int jj = 0; jj < 8; jj++) {
            float e00 = __expf(sc[2*jj][0]),   e01 = __expf(sc[2*jj][1]);
            float e02 = __expf(sc[2*jj][2]),   e03 = __expf(sc[2*jj][3]);
            float e10 = __expf(sc[2*jj+1][0]), e11 = __expf(sc[2*jj+1][1]);
            float e12 = __expf(sc[2*jj+1][2]), e13 = __expf(sc[2*jj+1][3]);
            ls0 += (e00 + e01) + (e10 + e11);
            ls1 += (e02 + e03) + (e12 + e13);
            pa[jj][0] = packbf(e00, e01);
            pa[jj][1] = packbf(e02, e03);
            pa[jj][2] = packbf(e10, e11);
            pa[jj][3] = packbf(e12, e13);
        }

        // ---- MMA2: O[16,64] += P @ V ----
#pragma unroll
        for (int kk = 0; kk < 8; kk++) {
#pragma unroll
            for (int jj = 0; jj < 4; jj++) {
                uint32_t bb[4];
                ldsm4t(bb, Vsu + (uint32_t)(kk*2048 + l15*128) + sw16[jj]);
                mma16816(oc[2*jj],     pa[kk], bb[0], bb[1]);
                mma16816(oc[2*jj + 1], pa[kk], bb[2], bb[3]);
            }
        }

        __syncthreads();   // all readers done before overwriting buf (t&1)
        if (t + 2 < 32) {
            LOAD_TILE(t + 2, t & 1);
            CP_COMMIT();
            CP_WAIT(1);    // tile t+1 guaranteed complete
        } else {
            CP_WAIT(0);
        }
        __syncthreads();
    }
#undef LOAD_TILE

    // rowsum reduce across the quad (lanes sharing a row)
    ls0 += __shfl_xor_sync(0xffffffffu, ls0, 1);
    ls0 += __shfl_xor_sync(0xffffffffu, ls0, 2);
    ls1 += __shfl_xor_sync(0xffffffffu, ls1, 1);
    ls1 += __shfl_xor_sync(0xffffffffu, ls1, 2);
    const float inv0 = 1.0f / ls0, inv1 = 1.0f / ls1;

    const int r = lane >> 2, q = lane & 3;
    const int row0 = m0 + 16*wid + r;
#pragma unroll
    for (int j = 0; j < 8; j++) {
        int d = 8*j + 2*q;
        *(float2*)(Op + (size_t)row0 * DKH + d) =
            make_float2(oc[j][0] * inv0, oc[j][1] * inv0);
        *(float2*)(Op + (size_t)(row0 + 8) * DKH + d) =
            make_float2(oc[j][2] * inv1, oc[j][3] * inv1);
    }
}

// ---------------------------------------------------------------------------
// Residual add + LayerNorm (biased variance, eps=1e-5), one CTA per row
// ---------------------------------------------------------------------------
__global__ __launch_bounds__(256) void ln_kernel(
    const float* __restrict__ x,
    const float* __restrict__ gamma,
    const float* __restrict__ beta,
    float* __restrict__ out)
{
    const int row = blockIdx.x;
    const int tid = threadIdx.x;
    const float* ao = g_AO + (size_t)row * DM;
    const float* xr = x    + (size_t)row * DM;

    float v[3];
    float sum = 0.f, ss = 0.f;
    int k = 0;
    for (int i = tid; i < DM; i += 256, k++) {
        float val = ao[i] + xr[i];
        v[k] = val;
        sum += val;
        ss  += val * val;
    }

#pragma unroll
    for (int off = 16; off > 0; off >>= 1) {
        sum += __shfl_xor_sync(0xffffffffu, sum, off);
        ss  += __shfl_xor_sync(0xffffffffu, ss,  off);
    }
    __shared__ float s1[8], s2[8];
    const int w = tid >> 5, lane = tid & 31;
    if (lane == 0) { s1[w] = sum; s2[w] = ss; }
    __syncthreads();
    if (w == 0) {
        sum = s1[lane & 7];
        ss  = s2[lane & 7];
#pragma unroll
        for (int off = 4; off > 0; off >>= 1) {
            sum += __shfl_xor_sync(0xffffffffu, sum, off);
            ss  += __shfl_xor_sync(0xffffffffu, ss,  off);
        }
        if (lane == 0) { s1[0] = sum; s2[0] = ss; }
    }
    __syncthreads();
    sum = s1[0]; ss = s2[0];

    const float mean = sum * (1.0f / DM);
    const float var  = ss * (1.0f / DM) - mean * mean;
    const float rstd = rsqrtf(var + 1e-5f);

    k = 0;
    for (int i = tid; i < DM; i += 256, k++) {
        out[(size_t)row * DM + i] = (v[k] - mean) * rstd * gamma[i] + beta[i];
    }
}

// ---------------------------------------------------------------------------
extern "C" void kernel_launch(void* const* d_in, const int* in_sizes, int n_in,
                              void* d_out, int out_size)
{
    const float* x     = (const float*)d_in[0];
    const float* Wq    = (const float*)d_in[1];
    const float* Wk    = (const float*)d_in[2];
    const float* Wv    = (const float*)d_in[3];
    const float* gamma = (const float*)d_in[4];
    const float* beta  = (const float*)d_in[5];
    float* out = (float*)d_out;

    const int qkv_smem  = 65536;   // 2 x (16KB A + 16KB B)
    const int attn_smem = 81920;   // Qs 16KB + Ks 2x16KB + Vs 2x16KB
    cudaFuncSetAttribute(qkv_mma_kernel,
                         cudaFuncAttributeMaxDynamicSharedMemorySize, qkv_smem);
    cudaFuncSetAttribute(attn_mma_kernel,
                         cudaFuncAttributeMaxDynamicSharedMemorySize, attn_smem);

    qkv_mma_kernel<<<dim3(DM / 128, NT / 128, 3), 256, qkv_smem>>>(x, Wq, Wk, Wv);
    attn_mma_kernel<<<dim3(NT / 128, NH), 256, attn_smem>>>();
    ln_kernel<<<NT, 256>>>(x, gamma, beta, out);
}

// round 11
// speedup vs baseline: 5.6029x; 1.0009x over previous
#include <cuda_runtime.h>
#include <cuda_bf16.h>
#include <cstdint>

#define NT  4096
#define DM  640
#define NH  10
#define DKH 64
#define HS  (NT * DKH)

// Scratch (allocation-free rule: __device__ globals). Q/K/V stored bf16.
__device__ __nv_bfloat16 g_Q[NT * DM];
__device__ __nv_bfloat16 g_K[NT * DM];
__device__ __nv_bfloat16 g_V[NT * DM];
__device__ float g_AO[NT * DM];

// ---------------------------------------------------------------------------
// Helpers (arch-neutral PTX: sm_80-era, accepted by target sm_103)
// ---------------------------------------------------------------------------
__device__ __forceinline__ uint32_t su32(const void* p) {
    uint32_t a;
    asm("{ .reg .u64 t; cvta.to.shared.u64 t, %1; cvt.u32.u64 %0, t; }"
        : "=r"(a) : "l"(p));
    return a;
}
// pack two f32 -> bf16x2 (lo = first arg)
__device__ __forceinline__ uint32_t packbf(float lo, float hi) {
    uint32_t r;
    asm("cvt.rn.bf16x2.f32 %0, %1, %2;" : "=r"(r) : "f"(hi), "f"(lo));
    return r;
}
__device__ __forceinline__ void ldsm4(uint32_t r[4], uint32_t a) {
    asm volatile("ldmatrix.sync.aligned.m8n8.x4.shared.b16 {%0,%1,%2,%3}, [%4];"
        : "=r"(r[0]), "=r"(r[1]), "=r"(r[2]), "=r"(r[3]) : "r"(a));
}
__device__ __forceinline__ void ldsm4t(uint32_t r[4], uint32_t a) {
    asm volatile("ldmatrix.sync.aligned.m8n8.x4.trans.shared.b16 {%0,%1,%2,%3}, [%4];"
        : "=r"(r[0]), "=r"(r[1]), "=r"(r[2]), "=r"(r[3]) : "r"(a));
}
__device__ __forceinline__ void mma16816(float* c, const uint32_t* a,
                                         uint32_t b0, uint32_t b1) {
    asm volatile("mma.sync.aligned.m16n8k16.row.col.f32.bf16.bf16.f32 "
        "{%0,%1,%2,%3}, {%4,%5,%6,%7}, {%8,%9}, {%0,%1,%2,%3};"
        : "+f"(c[0]), "+f"(c[1]), "+f"(c[2]), "+f"(c[3])
        : "r"(a[0]), "r"(a[1]), "r"(a[2]), "r"(a[3]), "r"(b0), "r"(b1));
}
__device__ __forceinline__ void cpa16(uint32_t s, const void* g) {
    asm volatile("cp.async.cg.shared.global [%0], [%1], 16;"
                 :: "r"(s), "l"(g) : "memory");
}
#define CP_COMMIT() asm volatile("cp.async.commit_group;" ::: "memory")
#define CP_WAIT(n)  asm volatile("cp.async.wait_group %0;" :: "n"(n) : "memory")

// ---------------------------------------------------------------------------
// QKV projection: C = x @ W^T (bf16 HMMA, fp32 accum), C stored bf16.
// BM=128, BN=128, BK=64, 256 threads (warp grid 2m x 4n, warp tile 64x32).
// Smem rows: [row][64k] bf16 = 128B, 16B-chunk swizzle c ^= row&7.
// ---------------------------------------------------------------------------
__global__ __launch_bounds__(256, 1) void qkv_mma_kernel(
    const float* __restrict__ x,  const float* __restrict__ Wq,
    const float* __restrict__ Wk, const float* __restrict__ Wv)
{
    extern __shared__ char dynsm[];   // 2 x (As 16KB + Bs 16KB) = 64KB

    const float* W; __nv_bfloat16* C; float cs;
    if (blockIdx.z == 0)      { W = Wq; C = g_Q; cs = 0.015625f; }  // fold 1/sqrt(N)
    else if (blockIdx.z == 1) { W = Wk; C = g_K; cs = 1.0f; }
    else                      { W = Wv; C = g_V; cs = 1.0f; }

    const int m0 = blockIdx.y * 128, n0 = blockIdx.x * 128;
    const int tid = threadIdx.x, lane = tid & 31, wid = tid >> 5;
    const int wm = wid & 1, wn = wid >> 1;
    const int l7 = lane & 7, l15 = lane & 15, hi = lane >> 4;
    const uint32_t smb = su32(dynsm);

    // loader: thread -> (row = tid/2, k-half = (tid&1)*32)
    const int lrow = tid >> 1, kh = (tid & 1) * 32;
    const float* xs = x + (size_t)(m0 + lrow) * DM + kh;
    const float* ws = W + (size_t)(n0 + lrow) * DM + kh;

    uint32_t stoff[4];
#pragma unroll
    for (int i = 0; i < 4; i++) {
        int c = 4 * (tid & 1) + i;
        stoff[i] = (uint32_t)(lrow * 128 + ((c ^ (lrow & 7)) * 16));
    }

    float acc[4][4][4];
#pragma unroll
    for (int i = 0; i < 4; i++)
#pragma unroll
        for (int j = 0; j < 4; j++)
#pragma unroll
            for (int k = 0; k < 4; k++) acc[i][j][k] = 0.f;

    uint32_t pkA[16], pkB[16];
#pragma unroll
    for (int i = 0; i < 8; i++) {
        float4 a = *(const float4*)(xs + i * 4);
        float4 b = *(const float4*)(ws + i * 4);
        pkA[2*i] = packbf(a.x, a.y); pkA[2*i+1] = packbf(a.z, a.w);
        pkB[2*i] = packbf(b.x, b.y); pkB[2*i+1] = packbf(b.z, b.w);
    }

    for (int kc = 0; kc < 10; kc++) {
        char* bufA = dynsm + (kc & 1) * 32768;
        char* bufB = bufA + 16384;
        const uint32_t Asu = smb + (kc & 1) * 32768;
        const uint32_t Bsu = Asu + 16384;
#pragma unroll
        for (int i = 0; i < 4; i++) {
            *(uint4*)(bufA + stoff[i]) =
                make_uint4(pkA[4*i], pkA[4*i+1], pkA[4*i+2], pkA[4*i+3]);
            *(uint4*)(bufB + stoff[i]) =
                make_uint4(pkB[4*i], pkB[4*i+1], pkB[4*i+2], pkB[4*i+3]);
        }
        __syncthreads();

        if (kc < 9) {
            const float* xs2 = xs + (kc + 1) * 64;
            const float* ws2 = ws + (kc + 1) * 64;
#pragma unroll
            for (int i = 0; i < 8; i++) {
                float4 a = *(const float4*)(xs2 + i * 4);
                float4 b = *(const float4*)(ws2 + i * 4);
                pkA[2*i] = packbf(a.x, a.y); pkA[2*i+1] = packbf(a.z, a.w);
                pkB[2*i] = packbf(b.x, b.y); pkB[2*i+1] = packbf(b.z, b.w);
            }
        }

#pragma unroll
        for (int kk = 0; kk < 4; kk++) {
            uint32_t af[4][4];
#pragma unroll
            for (int mi = 0; mi < 4; mi++)
                ldsm4(af[mi], Asu + (uint32_t)((wm*64 + mi*16 + l15) * 128
                              + (((2*kk + hi) ^ l7) * 16)));
            uint32_t bf2[2][4];
#pragma unroll
            for (int bi = 0; bi < 2; bi++)
                ldsm4(bf2[bi], Bsu + (uint32_t)((wn*32 + bi*16 + hi*8 + l7) * 128
                               + (((2*kk + ((lane >> 3) & 1)) ^ l7) * 16)));
#pragma unroll
            for (int mi = 0; mi < 4; mi++) {
                mma16816(acc[mi][0], af[mi], bf2[0][0], bf2[0][1]);
                mma16816(acc[mi][1], af[mi], bf2[0][2], bf2[0][3]);
                mma16816(acc[mi][2], af[mi], bf2[1][0], bf2[1][1]);
                mma16816(acc[mi][3], af[mi], bf2[1][2], bf2[1][3]);
            }
        }
        __syncthreads();
    }

    // epilogue: pack fp32 -> bf16 pairs, store
    const int r = lane >> 2, q = lane & 3;
#pragma unroll
    for (int mi = 0; mi < 4; mi++) {
        int row0 = m0 + wm*64 + mi*16 + r;
#pragma unroll
        for (int ni = 0; ni < 4; ni++) {
            int col = n0 + wn*32 + ni*8 + 2*q;
            uint32_t p0 = packbf(acc[mi][ni][0]*cs, acc[mi][ni][1]*cs);
            uint32_t p1 = packbf(acc[mi][ni][2]*cs, acc[mi][ni][3]*cs);
            *(uint32_t*)&C[(size_t)row0 * DM + col] = p0;
            *(uint32_t*)&C[(size_t)(row0 + 8) * DM + col] = p1;
        }
    }
}

// ---------------------------------------------------------------------------
// Fused attention (flat-reshape head semantics), bf16 HMMA.
// Per CTA: one head x 128 Q rows. 8 warps, each owns a 16-row stripe.
// Ks smem [64 d][128 key] = K native layout; Vs [128 key][64 d] = V native.
// Both feed ldmatrix.trans B-frags directly; P repacked in registers.
// ---------------------------------------------------------------------------
__global__ __launch_bounds__(256, 1) void attn_mma_kernel()
{
    extern __shared__ char dynsm[];
    // Qs 16KB | Ks[2] 2x16KB | Vs[2] 2x16KB  -> 80KB
    const uint32_t smQ = su32(dynsm);
    const uint32_t smK = smQ + 16384;
    const uint32_t smV = smQ + 49152;

    const int h  = blockIdx.y;
    const int m0 = blockIdx.x * 128;
    const __nv_bfloat16* Qp = g_Q + (size_t)h * HS;
    const __nv_bfloat16* Kp = g_K + (size_t)h * HS;
    const __nv_bfloat16* Vp = g_V + (size_t)h * HS;
    float* Op = g_AO + (size_t)h * HS;

    const int tid = threadIdx.x, lane = tid & 31, wid = tid >> 5;
    const int l7 = lane & 7, l15 = lane & 15, hi = lane >> 4;

    uint32_t sw16[8];
#pragma unroll
    for (int j = 0; j < 8; j++) sw16[j] = (uint32_t)(((2*j + hi) ^ l7) * 16);

    // ---- prologue: async Q + tiles 0,1 ----
#pragma unroll
    for (int i = 0; i < 4; i++) {
        int idx = tid + 256 * i;
        int row = idx >> 3, c = idx & 7;
        cpa16(smQ + row*128 + ((c ^ (row & 7)) * 16),
              Qp + (size_t)(m0 + row) * DKH + c*8);
    }
    CP_COMMIT();

#define LOAD_TILE(TT, B) do {                                              \
    int nb = (TT) * 128;                                                   \
    _Pragma("unroll")                                                      \
    for (int i = 0; i < 4; i++) {                                          \
        int idx = tid + 256 * i;                                           \
        int row = idx >> 4, c = idx & 15;                                  \
        cpa16(smK + (B)*16384 + row*256 + ((c ^ (row & 7)) * 16),          \
              Kp + (size_t)row * NT + nb + c*8);                           \
    }                                                                      \
    _Pragma("unroll")                                                      \
    for (int i = 0; i < 4; i++) {                                          \
        int idx = tid + 256 * i;                                           \
        int row = idx >> 3, c = idx & 7;                                   \
        cpa16(smV + (B)*16384 + row*128 + ((c ^ (row & 7)) * 16),          \
              Vp + (size_t)(nb + row) * DKH + c*8);                        \
    }                                                                      \
} while (0)

    LOAD_TILE(0, 0); CP_COMMIT();
    LOAD_TILE(1, 1); CP_COMMIT();
    CP_WAIT(1);            // Q + tile0 ready
    __syncthreads();

    // Q fragments (persistent)
    uint32_t qa[4][4];
#pragma unroll
    for (int kk = 0; kk < 4; kk++)
        ldsm4(qa[kk], smQ + (uint32_t)((16*wid + l15) * 128) + sw16[kk]);

    float oc[8][4];
#pragma unroll
    for (int j = 0; j < 8; j++)
#pragma unroll
        for (int k = 0; k < 4; k++) oc[j][k] = 0.f;
    float ls0 = 0.f, ls1 = 0.f;

    for (int t = 0; t < 32; t++) {
        const uint32_t Ksu = smK + (uint32_t)(t & 1) * 16384;
        const uint32_t Vsu = smV + (uint32_t)(t & 1) * 16384;

        // ---- MMA1: S[16,128] = Q @ K' ----
        float sc[16][4];
#pragma unroll
        for (int j = 0; j < 16; j++)
#pragma unroll
            for (int k = 0; k < 4; k++) sc[j][k] = 0.f;

#pragma unroll
        for (int kk = 0; kk < 4; kk++) {
#pragma unroll
            for (int jj = 0; jj < 8; jj++) {
                uint32_t bb[4];
                ldsm4t(bb, Ksu + (uint32_t)(kk*4096 + l15*256) + sw16[jj]);
                mma16816(sc[2*jj],     qa[kk], bb[0], bb[1]);
                mma16816(sc[2*jj + 1], qa[kk], bb[2], bb[3]);
            }
        }

        // ---- exp + register repack to P A-frags + rowsum ----
        uint32_t pa[8][4];
#pragma unroll
        for (int jj = 0; jj < 8; jj++) {
            float e00 = __expf(sc[2*jj][0]),   e01 = __expf(sc[2*jj][1]);
            float e02 = __expf(sc[2*jj][2]),   e03 = __expf(sc[2*jj][3]);
            float e10 = __expf(sc[2*jj+1][0]), e11 = __expf(sc[2*jj+1][1]);
            float e12 = __expf(sc[2*jj+1][2]), e13 = __expf(sc[2*jj+1][3]);
            ls0 += (e00 + e01) + (e10 + e11);
            ls1 += (e02 + e03) + (e12 + e13);
            pa[jj][0] = packbf(e00, e01);
            pa[jj][1] = packbf(e02, e03);
            pa[jj][2] = packbf(e10, e11);
            pa[jj][3] = packbf(e12, e13);
        }

        // ---- MMA2: O[16,64] += P @ V ----
#pragma unroll
        for (int kk = 0; kk < 8; kk++) {
#pragma unroll
            for (int jj = 0; jj < 4; jj++) {
                uint32_t bb[4];
                ldsm4t(bb, Vsu + (uint32_t)(kk*2048 + l15*128) + sw16[jj]);
                mma16816(oc[2*jj],     pa[kk], bb[0], bb[1]);
                mma16816(oc[2*jj + 1], pa[kk], bb[2], bb[3]);
            }
        }

        __syncthreads();   // all readers done before overwriting buf (t&1)
        if (t + 2 < 32) {
            LOAD_TILE(t + 2, t & 1);
            CP_COMMIT();
            CP_WAIT(1);    // tile t+1 guaranteed complete
        } else {
            CP_WAIT(0);
        }
        __syncthreads();
    }
#undef LOAD_TILE

    // rowsum reduce across the quad (lanes sharing a row)
    ls0 += __shfl_xor_sync(0xffffffffu, ls0, 1);
    ls0 += __shfl_xor_sync(0xffffffffu, ls0, 2);
    ls1 += __shfl_xor_sync(0xffffffffu, ls1, 1);
    ls1 += __shfl_xor_sync(0xffffffffu, ls1, 2);
    const float inv0 = 1.0f / ls0, inv1 = 1.0f / ls1;

    const int r = lane >> 2, q = lane & 3;
    const int row0 = m0 + 16*wid + r;
#pragma unroll
    for (int j = 0; j < 8; j++) {
        int d = 8*j + 2*q;
        *(float2*)(Op + (size_t)row0 * DKH + d) =
            make_float2(oc[j][0] * inv0, oc[j][1] * inv0);
        *(float2*)(Op + (size_t)(row0 + 8) * DKH + d) =
            make_float2(oc[j][2] * inv1, oc[j][3] * inv1);
    }
}

// ---------------------------------------------------------------------------
// Residual add + LayerNorm (biased variance, eps=1e-5), one CTA per row
// ---------------------------------------------------------------------------
__global__ __launch_bounds__(256) void ln_kernel(
    const float* __restrict__ x,
    const float* __restrict__ gamma,
    const float* __restrict__ beta,
    float* __restrict__ out)
{
    const int row = blockIdx.x;
    const int tid = threadIdx.x;
    const float* ao = g_AO + (size_t)row * DM;
    const float* xr = x    + (size_t)row * DM;

    float v[3];
    float sum = 0.f, ss = 0.f;
    int k = 0;
    for (int i = tid; i < DM; i += 256, k++) {
        float val = ao[i] + xr[i];
        v[k] = val;
        sum += val;
        ss  += val * val;
    }

#pragma unroll
    for (int off = 16; off > 0; off >>= 1) {
        sum += __shfl_xor_sync(0xffffffffu, sum, off);
        ss  += __shfl_xor_sync(0xffffffffu, ss,  off);
    }
    __shared__ float s1[8], s2[8];
    const int w = tid >> 5, lane = tid & 31;
    if (lane == 0) { s1[w] = sum; s2[w] = ss; }
    __syncthreads();
    if (w == 0) {
        sum = s1[lane & 7];
        ss  = s2[lane & 7];
#pragma unroll
        for (int off = 4; off > 0; off >>= 1) {
            sum += __shfl_xor_sync(0xffffffffu, sum, off);
            ss  += __shfl_xor_sync(0xffffffffu, ss,  off);
        }
        if (lane == 0) { s1[0] = sum; s2[0] = ss; }
    }
    __syncthreads();
    sum = s1[0]; ss = s2[0];

    const float mean = sum * (1.0f / DM);
    const float var  = ss * (1.0f / DM) - mean * mean;
    const float rstd = rsqrtf(var + 1e-5f);

    k = 0;
    for (int i = tid; i < DM; i += 256, k++) {
        out[(size_t)row * DM + i] = (v[k] - mean) * rstd * gamma[i] + beta[i];
    }
}

// ---------------------------------------------------------------------------
extern "C" void kernel_launch(void* const* d_in, const int* in_sizes, int n_in,
                              void* d_out, int out_size)
{
    const float* x     = (const float*)d_in[0];
    const float* Wq    = (const float*)d_in[1];
    const float* Wk    = (const float*)d_in[2];
    const float* Wv    = (const float*)d_in[3];
    const float* gamma = (const float*)d_in[4];
    const float* beta  = (const float*)d_in[5];
    float* out = (float*)d_out;

    const int qkv_smem  = 65536;   // 2 x (16KB A + 16KB B)
    const int attn_smem = 81920;   // Qs 16KB + Ks 2x16KB + Vs 2x16KB
    cudaFuncSetAttribute(qkv_mma_kernel,
                         cudaFuncAttributeMaxDynamicSharedMemorySize, qkv_smem);
    cudaFuncSetAttribute(attn_mma_kernel,
                         cudaFuncAttributeMaxDynamicSharedMemorySize, attn_smem);

    qkv_mma_kernel<<<dim3(DM / 128, NT / 128, 3), 256, qkv_smem>>>(x, Wq, Wk, Wv);
    attn_mma_kernel<<<dim3(NT / 128, NH), 256, attn_smem>>>();
    ln_kernel<<<NT, 256>>>(x, gamma, beta, out);
}